// round 7
// baseline (speedup 1.0000x reference)
#include <cuda_runtime.h>
#include <cuda_fp16.h>
#include <math.h>
#include <stdint.h>

#define MAXN 100000
#define MAXE 1600000
#define D 128
#define SCAN_CHUNK 4096

// SW128 swizzle: XOR bits[6:4] with bits[9:7]
#define SW(o) ((o) ^ ((((unsigned)(o)) >> 3) & 0x70u))

// ---------------- device scratch ----------------
__device__ uint2 g_hh[(size_t)MAXN * 32]; // projected features, fp16x2 packed (256B/row)
__device__ float g_x[(size_t)MAXN * D];   // layer activations
__device__ float g_as[MAXN];
__device__ float g_ad[MAXN];
__device__ int   g_csr_src[MAXE];
__device__ int   g_rowptr[MAXN + 1];
__device__ int   g_cursor[MAXN];
__device__ int   g_deg[MAXN];
__device__ int   g_bsum[1024];
__device__ int   g_boff[1024];
__device__ float g_bnsum[D];
__device__ float g_bnsq[D];
__device__ float g_scale[D];
__device__ float g_shift[D];
__device__ int   g_flag;                  // 1 => edge_index stored as int32
__device__ unsigned char g_wimg[3 * 2 * 32768]; // pre-split swizzled W images

// ---------------- init + dtype detection (fused) ----------------
__global__ void zero_kernel(const unsigned* __restrict__ ei, int n) {
    int i = blockIdx.x * blockDim.x + threadIdx.x;
    if (i < n) g_deg[i] = 0;
    if (i < D) { g_bnsum[i] = 0.f; g_bnsq[i] = 0.f; }
    if (blockIdx.x == 0) {
        // int64 nonneg => every odd 32-bit word is 0; random int32 ids => never.
        __shared__ int found;
        if (threadIdx.x == 0) found = 0;
        __syncthreads();
        if (ei[2 * threadIdx.x + 1] != 0u) found = 1;
        __syncthreads();
        if (threadIdx.x == 0) g_flag = found;
    }
}

__device__ __forceinline__ int load_idx(const void* ei, long long pos) {
    if (g_flag) return ((const int*)ei)[pos];
    return (int)((const long long*)ei)[pos];
}

__global__ void count_kernel(const void* __restrict__ ei, int E) {
    int i = blockIdx.x * blockDim.x + threadIdx.x;
    if (i >= E) return;
    int dst = load_idx(ei, (long long)E + i);
    atomicAdd(&g_deg[dst], 1);
}

// ---- build split-fp16 swizzled W images ----
__global__ void prep_w_kernel(const float* __restrict__ Ws) {
    int idx = blockIdx.x * blockDim.x + threadIdx.x;   // [l][k][n]
    if (idx >= 3 * D * D) return;
    int l = idx >> 14;
    int k = (idx >> 7) & 127;
    int nn = idx & 127;
    float f = Ws[idx];
    __half h = __float2half_rn(f);
    __half lo = __float2half_rn(f - __half2float(h));
    int kc = k >> 6, kl = k & 63;
    unsigned o = SW((unsigned)(nn * 128 + kl * 2));
    size_t base = (size_t)l * 65536 + (size_t)kc * 32768;
    *(__half*)(g_wimg + base + o) = h;
    *(__half*)(g_wimg + base + 16384 + o) = lo;
}

// ---- multi-block scan ----
__global__ void scan_reduce_kernel(int n) {
    __shared__ int wsum[32];
    int tid = threadIdx.x, lane = tid & 31, wid = tid >> 5;
    int base = blockIdx.x * SCAN_CHUNK + tid * 4;
    int s = 0;
    #pragma unroll
    for (int k = 0; k < 4; k++) {
        int idx = base + k;
        if (idx < n) s += g_deg[idx];
    }
    #pragma unroll
    for (int o = 16; o > 0; o >>= 1) s += __shfl_xor_sync(0xffffffffu, s, o);
    if (lane == 0) wsum[wid] = s;
    __syncthreads();
    if (wid == 0) {
        int v = wsum[lane];
        #pragma unroll
        for (int o = 16; o > 0; o >>= 1) v += __shfl_xor_sync(0xffffffffu, v, o);
        if (lane == 0) g_bsum[blockIdx.x] = v;
    }
}

__global__ void scan_top_kernel(int nb, int n) {
    __shared__ int wsum[32];
    int tid = threadIdx.x, lane = tid & 31, wid = tid >> 5;
    int v = (tid < nb) ? g_bsum[tid] : 0;
    int incl = v;
    #pragma unroll
    for (int o = 1; o < 32; o <<= 1) {
        int t = __shfl_up_sync(0xffffffffu, incl, o);
        if (lane >= o) incl += t;
    }
    if (lane == 31) wsum[wid] = incl;
    __syncthreads();
    if (wid == 0) {
        int s = wsum[lane];
        #pragma unroll
        for (int o = 1; o < 32; o <<= 1) {
            int t = __shfl_up_sync(0xffffffffu, s, o);
            if (lane >= o) s += t;
        }
        wsum[lane] = s;
    }
    __syncthreads();
    int excl = (wid > 0 ? wsum[wid - 1] : 0) + incl - v;
    if (tid < nb) g_boff[tid] = excl;
    if (tid == nb - 1) g_rowptr[n] = excl + v;
}

__global__ void scan_apply_kernel(int n) {
    __shared__ int wsum[32];
    int tid = threadIdx.x, lane = tid & 31, wid = tid >> 5;
    int base = blockIdx.x * SCAN_CHUNK + tid * 4;
    int v[4];
    int tsum = 0;
    #pragma unroll
    for (int k = 0; k < 4; k++) {
        int idx = base + k;
        v[k] = (idx < n) ? g_deg[idx] : 0;
        tsum += v[k];
    }
    int incl = tsum;
    #pragma unroll
    for (int o = 1; o < 32; o <<= 1) {
        int t = __shfl_up_sync(0xffffffffu, incl, o);
        if (lane >= o) incl += t;
    }
    if (lane == 31) wsum[wid] = incl;
    __syncthreads();
    if (wid == 0) {
        int s = wsum[lane];
        #pragma unroll
        for (int o = 1; o < 32; o <<= 1) {
            int t = __shfl_up_sync(0xffffffffu, s, o);
            if (lane >= o) s += t;
        }
        wsum[lane] = s;
    }
    __syncthreads();
    int run = g_boff[blockIdx.x] + (wid > 0 ? wsum[wid - 1] : 0) + incl - tsum;
    #pragma unroll
    for (int k = 0; k < 4; k++) {
        int idx = base + k;
        if (idx < n) { g_rowptr[idx] = run; g_cursor[idx] = run; }
        run += v[k];
    }
}

__global__ void scatter_kernel(const void* __restrict__ ei, int E) {
    int i = blockIdx.x * blockDim.x + threadIdx.x;
    if (i >= E) return;
    int src = load_idx(ei, i);
    int dst = load_idx(ei, (long long)E + i);
    int pos = atomicAdd(&g_cursor[dst], 1);
    g_csr_src[pos] = src;
}

// ---------------- GEMM: split-fp16 tensor-core MMA ----------------
__device__ __forceinline__ void ldsm_x4(unsigned* r, unsigned addr) {
    asm volatile("ldmatrix.sync.aligned.m8n8.x4.shared.b16 {%0,%1,%2,%3}, [%4];"
                 : "=r"(r[0]), "=r"(r[1]), "=r"(r[2]), "=r"(r[3]) : "r"(addr));
}
__device__ __forceinline__ void ldsm_x2(unsigned* r, unsigned addr) {
    asm volatile("ldmatrix.sync.aligned.m8n8.x2.shared.b16 {%0,%1}, [%2];"
                 : "=r"(r[0]), "=r"(r[1]) : "r"(addr));
}
__device__ __forceinline__ void mma16816(float* c, const unsigned* a, const unsigned* b) {
    asm volatile("mma.sync.aligned.m16n8k16.row.col.f32.f16.f16.f32 "
                 "{%0,%1,%2,%3}, {%4,%5,%6,%7}, {%8,%9}, {%0,%1,%2,%3};"
                 : "+f"(c[0]), "+f"(c[1]), "+f"(c[2]), "+f"(c[3])
                 : "r"(a[0]), "r"(a[1]), "r"(a[2]), "r"(a[3]), "r"(b[0]), "r"(b[1]));
}

__global__ void __launch_bounds__(256)
gemm_kernel(const float* __restrict__ xext, int use_ext, int layer,
            const float* __restrict__ avs, const float* __restrict__ avd,
            int use_bn, int n) {
    __shared__ __align__(16) unsigned char sm[49152];
    unsigned ubase = (unsigned)__cvta_generic_to_shared(sm);
    const unsigned uXh = ubase, uXl = ubase + 8192;
    const unsigned uWh = ubase + 16384, uWl = ubase + 32768;

    const float* xsrc = use_ext ? xext : g_x;
    int tid = threadIdx.x;
    int row0 = blockIdx.x * 64;
    int warp = tid >> 5, lane = tid & 31;
    int g = warp >> 1;
    int nbase = (warp & 1) * 64;

    const float4* X4 = (const float4*)xsrc;

    float c[8][4];
    #pragma unroll
    for (int t = 0; t < 8; t++)
        #pragma unroll
        for (int r = 0; r < 4; r++) c[t][r] = 0.f;

    #pragma unroll
    for (int kc = 0; kc < 2; kc++) {
        // stage W: linear 32 KB uint4 copy from pre-built swizzled image
        {
            const uint4* wsrc = (const uint4*)(g_wimg + (size_t)layer * 65536 + (size_t)kc * 32768);
            uint4* wdst = (uint4*)(sm + 16384);
            #pragma unroll 8
            for (int i = tid; i < 2048; i += 256) wdst[i] = wsrc[i];
        }
        // stage X: BN+ReLU fused, split hi/lo, 8B packed stores
        for (int i = tid; i < 64 * 16; i += 256) {
            int r = i >> 4, c4 = i & 15;
            int gr = row0 + r;
            float4 v = make_float4(0.f, 0.f, 0.f, 0.f);
            if (gr < n) v = X4[(size_t)gr * 32 + kc * 16 + c4];
            if (use_bn) {
                float4 sc = ((const float4*)g_scale)[kc * 16 + c4];
                float4 sh = ((const float4*)g_shift)[kc * 16 + c4];
                v.x = fmaxf(fmaf(v.x, sc.x, sh.x), 0.f);
                v.y = fmaxf(fmaf(v.y, sc.y, sh.y), 0.f);
                v.z = fmaxf(fmaf(v.z, sc.z, sh.z), 0.f);
                v.w = fmaxf(fmaf(v.w, sc.w, sh.w), 0.f);
            }
            __half2 hA = __floats2half2_rn(v.x, v.y);
            __half2 hB = __floats2half2_rn(v.z, v.w);
            float2 fA = __half22float2(hA), fB = __half22float2(hB);
            __half2 lA = __floats2half2_rn(v.x - fA.x, v.y - fA.y);
            __half2 lB = __floats2half2_rn(v.z - fB.x, v.w - fB.y);
            unsigned o = SW((unsigned)(r * 128 + 8 * c4));
            uint2 ph, pl;
            ph.x = *(unsigned*)&hA; ph.y = *(unsigned*)&hB;
            pl.x = *(unsigned*)&lA; pl.y = *(unsigned*)&lB;
            *(uint2*)(sm + o) = ph;
            *(uint2*)(sm + 8192 + o) = pl;
        }
        __syncthreads();

        #pragma unroll
        for (int ki = 0; ki < 4; ki++) {
            unsigned ah[4], al[4];
            {
                unsigned rowA = (unsigned)(16 * g + (lane & 7) + ((lane >> 3) & 1) * 8);
                unsigned colA = (unsigned)(32 * ki + ((lane >> 4) & 1) * 16);
                unsigned off = SW(rowA * 128 + colA);
                ldsm_x4(ah, uXh + off);
                ldsm_x4(al, uXl + off);
            }
            #pragma unroll
            for (int nt = 0; nt < 8; nt++) {
                unsigned bh[2], bl[2];
                unsigned lb = lane & 15;
                unsigned rowB = (unsigned)(nbase + nt * 8 + (lb & 7));
                unsigned colB = (unsigned)(32 * ki + ((lb >> 3) & 1) * 16);
                unsigned off = SW(rowB * 128 + colB);
                ldsm_x2(bh, uWh + off);
                ldsm_x2(bl, uWl + off);
                mma16816(c[nt], ah, bh);
                mma16816(c[nt], ah, bl);
                mma16816(c[nt], al, bh);
            }
        }
        __syncthreads();
    }

    // epilogue: pack h to fp16; as/ad dots combined via smem
    float* sdot_s = (float*)sm;
    float* sdot_d = (float*)(sm + 512);
    int q = lane & 3;
    int rl = 16 * g + (lane >> 2);
    int rh = rl + 8;
    int grl = row0 + rl, grh = row0 + rh;
    float psl = 0.f, pdl = 0.f, psh = 0.f, pdh = 0.f;
    #pragma unroll
    for (int nt = 0; nt < 8; nt++) {
        int cn = nbase + nt * 8 + 2 * q;
        float a0 = avs[cn], a1 = avs[cn + 1];
        float d0 = avd[cn], d1 = avd[cn + 1];
        psl += c[nt][0] * a0 + c[nt][1] * a1;
        pdl += c[nt][0] * d0 + c[nt][1] * d1;
        psh += c[nt][2] * a0 + c[nt][3] * a1;
        pdh += c[nt][2] * d0 + c[nt][3] * d1;
        __half2 plo = __floats2half2_rn(c[nt][0], c[nt][1]);
        __half2 phi = __floats2half2_rn(c[nt][2], c[nt][3]);
        if (grl < n) ((unsigned*)g_hh)[(size_t)grl * 64 + (cn >> 1)] = *(unsigned*)&plo;
        if (grh < n) ((unsigned*)g_hh)[(size_t)grh * 64 + (cn >> 1)] = *(unsigned*)&phi;
    }
    psl += __shfl_xor_sync(0xffffffffu, psl, 1); psl += __shfl_xor_sync(0xffffffffu, psl, 2);
    pdl += __shfl_xor_sync(0xffffffffu, pdl, 1); pdl += __shfl_xor_sync(0xffffffffu, pdl, 2);
    psh += __shfl_xor_sync(0xffffffffu, psh, 1); psh += __shfl_xor_sync(0xffffffffu, psh, 2);
    pdh += __shfl_xor_sync(0xffffffffu, pdh, 1); pdh += __shfl_xor_sync(0xffffffffu, pdh, 2);
    int half = warp & 1;
    if (q == 0) {
        sdot_s[rl * 2 + half] = psl; sdot_d[rl * 2 + half] = pdl;
        sdot_s[rh * 2 + half] = psh; sdot_d[rh * 2 + half] = pdh;
    }
    __syncthreads();
    if (tid < 64) {
        int gr = row0 + tid;
        if (gr < n) {
            g_as[gr] = sdot_s[tid * 2] + sdot_s[tid * 2 + 1];
            g_ad[gr] = sdot_d[tid * 2] + sdot_d[tid * 2 + 1];
        }
    }
}

// ---------------- aggregation: warp per dst node; 16-lane halves each own an edge ----------------
__global__ void __launch_bounds__(256)
agg_kernel(const float* __restrict__ bias, float* __restrict__ outext,
           int use_ext, int do_bn, int n) {
    __shared__ float sb_sum[D];
    __shared__ float sb_sq[D];
    if (do_bn) {
        if (threadIdx.x < D) { sb_sum[threadIdx.x] = 0.f; sb_sq[threadIdx.x] = 0.f; }
        __syncthreads();
    }
    int warp = threadIdx.x >> 5, lane = threadIdx.x & 31;
    int half = lane >> 4, hl = lane & 15;
    int node = blockIdx.x * 8 + warp;
    float* out = use_ext ? outext : g_x;
    float o03 = 0.f, o14 = 0.f;   // dummies to keep compiler honest
    float oc[8];
    #pragma unroll
    for (int i = 0; i < 8; i++) oc[i] = 0.f;
    float ssum = 0.f;
    float b0x=0,b0y=0,b0z=0,b0w=0,b1x=0,b1y=0,b1z=0,b1w=0;
    (void)o03; (void)o14;

    if (node < n) {
        int beg = g_rowptr[node], end = g_rowptr[node + 1];
        float md = g_ad[node];
        // phase 1: segment max
        float m = -3.0e38f;
        for (int j = beg + lane; j < end; j += 32) {
            float e = g_as[g_csr_src[j]] + md;
            e = e > 0.f ? e : 0.2f * e;
            m = fmaxf(m, e);
        }
        #pragma unroll
        for (int o = 16; o > 0; o >>= 1) m = fmaxf(m, __shfl_xor_sync(0xffffffffu, m, o));

        // phase 2: 16-lane halves, uint4 row loads, 4 edges in flight
        const uint4* hb4 = (const uint4*)g_hh;   // row stride = 16 uint4
        int j = beg;
        for (; j + 4 <= end; j += 4) {
            int sA = g_csr_src[j],     sB = g_csr_src[j + 1];
            int sC = g_csr_src[j + 2], sD = g_csr_src[j + 3];
            int s0 = half ? sB : sA;
            int s1 = half ? sD : sC;
            uint4 p = hb4[(size_t)s0 * 16 + hl];
            uint4 r = hb4[(size_t)s1 * 16 + hl];
            float eA = g_as[sA] + md; eA = eA > 0.f ? eA : 0.2f * eA;
            float eB = g_as[sB] + md; eB = eB > 0.f ? eB : 0.2f * eB;
            float eC = g_as[sC] + md; eC = eC > 0.f ? eC : 0.2f * eC;
            float eD = g_as[sD] + md; eD = eD > 0.f ? eD : 0.2f * eD;
            float wA = __expf(eA - m), wB = __expf(eB - m);
            float wC = __expf(eC - m), wD = __expf(eD - m);
            ssum += (wA + wB) + (wC + wD);
            float w0 = half ? wB : wA;
            float w1 = half ? wD : wC;
            float2 f;
            f = __half22float2(*(__half2*)&p.x); oc[0] += f.x * w0; oc[1] += f.y * w0;
            f = __half22float2(*(__half2*)&p.y); oc[2] += f.x * w0; oc[3] += f.y * w0;
            f = __half22float2(*(__half2*)&p.z); oc[4] += f.x * w0; oc[5] += f.y * w0;
            f = __half22float2(*(__half2*)&p.w); oc[6] += f.x * w0; oc[7] += f.y * w0;
            f = __half22float2(*(__half2*)&r.x); oc[0] += f.x * w1; oc[1] += f.y * w1;
            f = __half22float2(*(__half2*)&r.y); oc[2] += f.x * w1; oc[3] += f.y * w1;
            f = __half22float2(*(__half2*)&r.z); oc[4] += f.x * w1; oc[5] += f.y * w1;
            f = __half22float2(*(__half2*)&r.w); oc[6] += f.x * w1; oc[7] += f.y * w1;
        }
        if (j + 2 <= end) {
            int sA = g_csr_src[j], sB = g_csr_src[j + 1];
            int s0 = half ? sB : sA;
            uint4 p = hb4[(size_t)s0 * 16 + hl];
            float eA = g_as[sA] + md; eA = eA > 0.f ? eA : 0.2f * eA;
            float eB = g_as[sB] + md; eB = eB > 0.f ? eB : 0.2f * eB;
            float wA = __expf(eA - m), wB = __expf(eB - m);
            ssum += wA + wB;
            float w0 = half ? wB : wA;
            float2 f;
            f = __half22float2(*(__half2*)&p.x); oc[0] += f.x * w0; oc[1] += f.y * w0;
            f = __half22float2(*(__half2*)&p.y); oc[2] += f.x * w0; oc[3] += f.y * w0;
            f = __half22float2(*(__half2*)&p.z); oc[4] += f.x * w0; oc[5] += f.y * w0;
            f = __half22float2(*(__half2*)&p.w); oc[6] += f.x * w0; oc[7] += f.y * w0;
            j += 2;
        }
        if (j < end) {
            int sA = g_csr_src[j];
            uint4 p = hb4[(size_t)sA * 16 + hl];
            float eA = g_as[sA] + md; eA = eA > 0.f ? eA : 0.2f * eA;
            float wA = __expf(eA - m);
            ssum += wA;
            float w0 = half ? 0.f : wA;   // only half 0 contributes
            float2 f;
            f = __half22float2(*(__half2*)&p.x); oc[0] += f.x * w0; oc[1] += f.y * w0;
            f = __half22float2(*(__half2*)&p.y); oc[2] += f.x * w0; oc[3] += f.y * w0;
            f = __half22float2(*(__half2*)&p.z); oc[4] += f.x * w0; oc[5] += f.y * w0;
            f = __half22float2(*(__half2*)&p.w); oc[6] += f.x * w0; oc[7] += f.y * w0;
        }
        // combine the two halves (channels match: lane&15)
        #pragma unroll
        for (int i = 0; i < 8; i++) oc[i] += __shfl_xor_sync(0xffffffffu, oc[i], 16);

        float inv = 1.f / (ssum + 1e-16f);
        float4 ba = ((const float4*)bias)[hl * 2];
        float4 bb = ((const float4*)bias)[hl * 2 + 1];
        b0x = oc[0] * inv + ba.x; b0y = oc[1] * inv + ba.y;
        b0z = oc[2] * inv + ba.z; b0w = oc[3] * inv + ba.w;
        b1x = oc[4] * inv + bb.x; b1y = oc[5] * inv + bb.y;
        b1z = oc[6] * inv + bb.z; b1w = oc[7] * inv + bb.w;
        if (half == 0) {
            float4* op = (float4*)(out + (size_t)node * D + hl * 8);
            op[0] = make_float4(b0x, b0y, b0z, b0w);
            op[1] = make_float4(b1x, b1y, b1z, b1w);
        }
    }

    if (do_bn) {
        if (node < n && half == 0) {
            int c = hl * 8;
            atomicAdd(&sb_sum[c + 0], b0x); atomicAdd(&sb_sq[c + 0], b0x * b0x);
            atomicAdd(&sb_sum[c + 1], b0y); atomicAdd(&sb_sq[c + 1], b0y * b0y);
            atomicAdd(&sb_sum[c + 2], b0z); atomicAdd(&sb_sq[c + 2], b0z * b0z);
            atomicAdd(&sb_sum[c + 3], b0w); atomicAdd(&sb_sq[c + 3], b0w * b0w);
            atomicAdd(&sb_sum[c + 4], b1x); atomicAdd(&sb_sq[c + 4], b1x * b1x);
            atomicAdd(&sb_sum[c + 5], b1y); atomicAdd(&sb_sq[c + 5], b1y * b1y);
            atomicAdd(&sb_sum[c + 6], b1z); atomicAdd(&sb_sq[c + 6], b1z * b1z);
            atomicAdd(&sb_sum[c + 7], b1w); atomicAdd(&sb_sq[c + 7], b1w * b1w);
        }
        __syncthreads();
        if (threadIdx.x < D) {
            atomicAdd(&g_bnsum[threadIdx.x], sb_sum[threadIdx.x]);
            atomicAdd(&g_bnsq[threadIdx.x], sb_sq[threadIdx.x]);
        }
    }
}

__global__ void bn_finalize_kernel(const float* __restrict__ gamma,
                                   const float* __restrict__ beta, float inv_n) {
    int c = threadIdx.x;
    float mean = g_bnsum[c] * inv_n;
    float var = g_bnsq[c] * inv_n - mean * mean;
    float sc = gamma[c] * rsqrtf(var + 1e-5f);
    g_scale[c] = sc;
    g_shift[c] = beta[c] - mean * sc;
    g_bnsum[c] = 0.f;
    g_bnsq[c] = 0.f;
}

// ---------------- launch ----------------
extern "C" void kernel_launch(void* const* d_in, const int* in_sizes, int n_in,
                              void* d_out, int out_size) {
    const float* x    = (const float*)d_in[0];
    const void*  ei   = d_in[1];
    const float* Ws   = (const float*)d_in[2];
    const float* a_s  = (const float*)d_in[3];
    const float* a_d  = (const float*)d_in[4];
    const float* bias = (const float*)d_in[5];
    const float* gam  = (const float*)d_in[6];
    const float* bet  = (const float*)d_in[7];
    float* out = (float*)d_out;

    int n = in_sizes[0] / D;
    int E = in_sizes[1] / 2;

    int nblk = (n + 255) / 256;
    int eblk = (E + 255) / 256;
    int gblk = (n + 63) / 64;
    int ablk = (n + 7) / 8;
    int sblk = (n + SCAN_CHUNK - 1) / SCAN_CHUNK;
    float inv_n = 1.0f / (float)n;

    // CSR build + W prep
    zero_kernel<<<nblk, 256>>>((const unsigned*)ei, n);
    prep_w_kernel<<<(3 * D * D + 255) / 256, 256>>>(Ws);
    count_kernel<<<eblk, 256>>>(ei, E);
    scan_reduce_kernel<<<sblk, 1024>>>(n);
    scan_top_kernel<<<1, 1024>>>(sblk, n);
    scan_apply_kernel<<<sblk, 1024>>>(n);
    scatter_kernel<<<eblk, 256>>>(ei, E);

    // layer 0
    gemm_kernel<<<gblk, 256>>>(x, 1, 0, a_s, a_d, 0, n);
    agg_kernel<<<ablk, 256>>>(bias, nullptr, 0, 1, n);
    bn_finalize_kernel<<<1, D>>>(gam, bet, inv_n);
    // layer 1
    gemm_kernel<<<gblk, 256>>>(nullptr, 0, 1, a_s + D, a_d + D, 1, n);
    agg_kernel<<<ablk, 256>>>(bias + D, nullptr, 0, 1, n);
    bn_finalize_kernel<<<1, D>>>(gam + D, bet + D, inv_n);
    // layer 2
    gemm_kernel<<<gblk, 256>>>(nullptr, 0, 2, a_s + 2 * D, a_d + 2 * D, 1, n);
    agg_kernel<<<ablk, 256>>>(bias + 2 * D, out, 1, 0, n);
}

// round 9
// speedup vs baseline: 1.0563x; 1.0563x over previous
#include <cuda_runtime.h>
#include <cuda_fp16.h>
#include <math.h>
#include <stdint.h>

#define MAXN 100000
#define MAXE 1600000
#define D 128
#define SCAN_CHUNK 4096

// SW128 swizzle: XOR bits[6:4] with bits[9:7]
#define SW(o) ((o) ^ ((((unsigned)(o)) >> 3) & 0x70u))

// ---------------- device scratch ----------------
__device__ uint2 g_hh[(size_t)MAXN * 32]; // projected features, fp16x2 packed (256B/row)
__device__ float g_x[(size_t)MAXN * D];   // layer activations
__device__ float g_as[MAXN];
__device__ float g_ad[MAXN];
__device__ int   g_csr_src[MAXE];
__device__ int   g_rowptr[MAXN + 1];
__device__ int   g_cursor[MAXN];
__device__ int   g_deg[MAXN];
__device__ int   g_bsum[1024];
__device__ int   g_boff[1024];
__device__ float g_bnsum[D];
__device__ float g_bnsq[D];
__device__ float g_scale[D];
__device__ float g_shift[D];
__device__ int   g_flag;                  // 1 => edge_index stored as int32
__device__ unsigned char g_wimg[3 * 2 * 32768]; // pre-split swizzled W images

// ---------------- init + dtype detection (fused) ----------------
__global__ void zero_kernel(const unsigned* __restrict__ ei, int n) {
    int i = blockIdx.x * blockDim.x + threadIdx.x;
    if (i < n) g_deg[i] = 0;
    if (i < D) { g_bnsum[i] = 0.f; g_bnsq[i] = 0.f; }
    if (blockIdx.x == 0) {
        __shared__ int found;
        if (threadIdx.x == 0) found = 0;
        __syncthreads();
        if (ei[2 * threadIdx.x + 1] != 0u) found = 1;
        __syncthreads();
        if (threadIdx.x == 0) g_flag = found;
    }
}

__device__ __forceinline__ int load_idx(const void* ei, long long pos) {
    if (g_flag) return ((const int*)ei)[pos];
    return (int)((const long long*)ei)[pos];
}

__global__ void count_kernel(const void* __restrict__ ei, int E) {
    int i = blockIdx.x * blockDim.x + threadIdx.x;
    if (i >= E) return;
    int dst = load_idx(ei, (long long)E + i);
    atomicAdd(&g_deg[dst], 1);
}

// ---- build split-fp16 swizzled W images ----
__global__ void prep_w_kernel(const float* __restrict__ Ws) {
    int idx = blockIdx.x * blockDim.x + threadIdx.x;   // [l][k][n]
    if (idx >= 3 * D * D) return;
    int l = idx >> 14;
    int k = (idx >> 7) & 127;
    int nn = idx & 127;
    float f = Ws[idx];
    __half h = __float2half_rn(f);
    __half lo = __float2half_rn(f - __half2float(h));
    int kc = k >> 6, kl = k & 63;
    unsigned o = SW((unsigned)(nn * 128 + kl * 2));
    size_t base = (size_t)l * 65536 + (size_t)kc * 32768;
    *(__half*)(g_wimg + base + o) = h;
    *(__half*)(g_wimg + base + 16384 + o) = lo;
}

// ---- multi-block scan ----
__global__ void scan_reduce_kernel(int n) {
    __shared__ int wsum[32];
    int tid = threadIdx.x, lane = tid & 31, wid = tid >> 5;
    int base = blockIdx.x * SCAN_CHUNK + tid * 4;
    int s = 0;
    #pragma unroll
    for (int k = 0; k < 4; k++) {
        int idx = base + k;
        if (idx < n) s += g_deg[idx];
    }
    #pragma unroll
    for (int o = 16; o > 0; o >>= 1) s += __shfl_xor_sync(0xffffffffu, s, o);
    if (lane == 0) wsum[wid] = s;
    __syncthreads();
    if (wid == 0) {
        int v = wsum[lane];
        #pragma unroll
        for (int o = 16; o > 0; o >>= 1) v += __shfl_xor_sync(0xffffffffu, v, o);
        if (lane == 0) g_bsum[blockIdx.x] = v;
    }
}

__global__ void scan_top_kernel(int nb, int n) {
    __shared__ int wsum[32];
    int tid = threadIdx.x, lane = tid & 31, wid = tid >> 5;
    int v = (tid < nb) ? g_bsum[tid] : 0;
    int incl = v;
    #pragma unroll
    for (int o = 1; o < 32; o <<= 1) {
        int t = __shfl_up_sync(0xffffffffu, incl, o);
        if (lane >= o) incl += t;
    }
    if (lane == 31) wsum[wid] = incl;
    __syncthreads();
    if (wid == 0) {
        int s = wsum[lane];
        #pragma unroll
        for (int o = 1; o < 32; o <<= 1) {
            int t = __shfl_up_sync(0xffffffffu, s, o);
            if (lane >= o) s += t;
        }
        wsum[lane] = s;
    }
    __syncthreads();
    int excl = (wid > 0 ? wsum[wid - 1] : 0) + incl - v;
    if (tid < nb) g_boff[tid] = excl;
    if (tid == nb - 1) g_rowptr[n] = excl + v;
}

__global__ void scan_apply_kernel(int n) {
    __shared__ int wsum[32];
    int tid = threadIdx.x, lane = tid & 31, wid = tid >> 5;
    int base = blockIdx.x * SCAN_CHUNK + tid * 4;
    int v[4];
    int tsum = 0;
    #pragma unroll
    for (int k = 0; k < 4; k++) {
        int idx = base + k;
        v[k] = (idx < n) ? g_deg[idx] : 0;
        tsum += v[k];
    }
    int incl = tsum;
    #pragma unroll
    for (int o = 1; o < 32; o <<= 1) {
        int t = __shfl_up_sync(0xffffffffu, incl, o);
        if (lane >= o) incl += t;
    }
    if (lane == 31) wsum[wid] = incl;
    __syncthreads();
    if (wid == 0) {
        int s = wsum[lane];
        #pragma unroll
        for (int o = 1; o < 32; o <<= 1) {
            int t = __shfl_up_sync(0xffffffffu, s, o);
            if (lane >= o) s += t;
        }
        wsum[lane] = s;
    }
    __syncthreads();
    int run = g_boff[blockIdx.x] + (wid > 0 ? wsum[wid - 1] : 0) + incl - tsum;
    #pragma unroll
    for (int k = 0; k < 4; k++) {
        int idx = base + k;
        if (idx < n) { g_rowptr[idx] = run; g_cursor[idx] = run; }
        run += v[k];
    }
}

__global__ void scatter_kernel(const void* __restrict__ ei, int E) {
    int i = blockIdx.x * blockDim.x + threadIdx.x;
    if (i >= E) return;
    int src = load_idx(ei, i);
    int dst = load_idx(ei, (long long)E + i);
    int pos = atomicAdd(&g_cursor[dst], 1);
    g_csr_src[pos] = src;
}

// ---------------- GEMM: split-fp16 tensor-core MMA ----------------
__device__ __forceinline__ void ldsm_x4(unsigned* r, unsigned addr) {
    asm volatile("ldmatrix.sync.aligned.m8n8.x4.shared.b16 {%0,%1,%2,%3}, [%4];"
                 : "=r"(r[0]), "=r"(r[1]), "=r"(r[2]), "=r"(r[3]) : "r"(addr));
}
__device__ __forceinline__ void ldsm_x2(unsigned* r, unsigned addr) {
    asm volatile("ldmatrix.sync.aligned.m8n8.x2.shared.b16 {%0,%1}, [%2];"
                 : "=r"(r[0]), "=r"(r[1]) : "r"(addr));
}
__device__ __forceinline__ void mma16816(float* c, const unsigned* a, const unsigned* b) {
    asm volatile("mma.sync.aligned.m16n8k16.row.col.f32.f16.f16.f32 "
                 "{%0,%1,%2,%3}, {%4,%5,%6,%7}, {%8,%9}, {%0,%1,%2,%3};"
                 : "+f"(c[0]), "+f"(c[1]), "+f"(c[2]), "+f"(c[3])
                 : "r"(a[0]), "r"(a[1]), "r"(a[2]), "r"(a[3]), "r"(b[0]), "r"(b[1]));
}

__global__ void __launch_bounds__(256)
gemm_kernel(const float* __restrict__ xext, int use_ext, int layer,
            const float* __restrict__ avs, const float* __restrict__ avd,
            int use_bn, int n) {
    __shared__ __align__(16) unsigned char sm[49152];
    unsigned ubase = (unsigned)__cvta_generic_to_shared(sm);
    const unsigned uXh = ubase, uXl = ubase + 8192;
    const unsigned uWh = ubase + 16384, uWl = ubase + 32768;

    const float* xsrc = use_ext ? xext : g_x;
    int tid = threadIdx.x;
    int row0 = blockIdx.x * 64;
    int warp = tid >> 5, lane = tid & 31;
    int g = warp >> 1;
    int nbase = (warp & 1) * 64;

    const float4* X4 = (const float4*)xsrc;

    float c[8][4];
    #pragma unroll
    for (int t = 0; t < 8; t++)
        #pragma unroll
        for (int r = 0; r < 4; r++) c[t][r] = 0.f;

    #pragma unroll
    for (int kc = 0; kc < 2; kc++) {
        {
            const uint4* wsrc = (const uint4*)(g_wimg + (size_t)layer * 65536 + (size_t)kc * 32768);
            uint4* wdst = (uint4*)(sm + 16384);
            #pragma unroll 8
            for (int i = tid; i < 2048; i += 256) wdst[i] = wsrc[i];
        }
        for (int i = tid; i < 64 * 16; i += 256) {
            int r = i >> 4, c4 = i & 15;
            int gr = row0 + r;
            float4 v = make_float4(0.f, 0.f, 0.f, 0.f);
            if (gr < n) v = X4[(size_t)gr * 32 + kc * 16 + c4];
            if (use_bn) {
                float4 sc = ((const float4*)g_scale)[kc * 16 + c4];
                float4 sh = ((const float4*)g_shift)[kc * 16 + c4];
                v.x = fmaxf(fmaf(v.x, sc.x, sh.x), 0.f);
                v.y = fmaxf(fmaf(v.y, sc.y, sh.y), 0.f);
                v.z = fmaxf(fmaf(v.z, sc.z, sh.z), 0.f);
                v.w = fmaxf(fmaf(v.w, sc.w, sh.w), 0.f);
            }
            __half2 hA = __floats2half2_rn(v.x, v.y);
            __half2 hB = __floats2half2_rn(v.z, v.w);
            float2 fA = __half22float2(hA), fB = __half22float2(hB);
            __half2 lA = __floats2half2_rn(v.x - fA.x, v.y - fA.y);
            __half2 lB = __floats2half2_rn(v.z - fB.x, v.w - fB.y);
            unsigned o = SW((unsigned)(r * 128 + 8 * c4));
            uint2 ph, pl;
            ph.x = *(unsigned*)&hA; ph.y = *(unsigned*)&hB;
            pl.x = *(unsigned*)&lA; pl.y = *(unsigned*)&lB;
            *(uint2*)(sm + o) = ph;
            *(uint2*)(sm + 8192 + o) = pl;
        }
        __syncthreads();

        #pragma unroll
        for (int ki = 0; ki < 4; ki++) {
            unsigned ah[4], al[4];
            {
                unsigned rowA = (unsigned)(16 * g + (lane & 7) + ((lane >> 3) & 1) * 8);
                unsigned colA = (unsigned)(32 * ki + ((lane >> 4) & 1) * 16);
                unsigned off = SW(rowA * 128 + colA);
                ldsm_x4(ah, uXh + off);
                ldsm_x4(al, uXl + off);
            }
            #pragma unroll
            for (int nt = 0; nt < 8; nt++) {
                unsigned bh[2], bl[2];
                unsigned lb = lane & 15;
                unsigned rowB = (unsigned)(nbase + nt * 8 + (lb & 7));
                unsigned colB = (unsigned)(32 * ki + ((lb >> 3) & 1) * 16);
                unsigned off = SW(rowB * 128 + colB);
                ldsm_x2(bh, uWh + off);
                ldsm_x2(bl, uWl + off);
                mma16816(c[nt], ah, bh);
                mma16816(c[nt], ah, bl);
                mma16816(c[nt], al, bh);
            }
        }
        __syncthreads();
    }

    float* sdot_s = (float*)sm;
    float* sdot_d = (float*)(sm + 512);
    int q = lane & 3;
    int rl = 16 * g + (lane >> 2);
    int rh = rl + 8;
    int grl = row0 + rl, grh = row0 + rh;
    float psl = 0.f, pdl = 0.f, psh = 0.f, pdh = 0.f;
    #pragma unroll
    for (int nt = 0; nt < 8; nt++) {
        int cn = nbase + nt * 8 + 2 * q;
        float a0 = avs[cn], a1 = avs[cn + 1];
        float d0 = avd[cn], d1 = avd[cn + 1];
        psl += c[nt][0] * a0 + c[nt][1] * a1;
        pdl += c[nt][0] * d0 + c[nt][1] * d1;
        psh += c[nt][2] * a0 + c[nt][3] * a1;
        pdh += c[nt][2] * d0 + c[nt][3] * d1;
        __half2 plo = __floats2half2_rn(c[nt][0], c[nt][1]);
        __half2 phi = __floats2half2_rn(c[nt][2], c[nt][3]);
        if (grl < n) ((unsigned*)g_hh)[(size_t)grl * 64 + (cn >> 1)] = *(unsigned*)&plo;
        if (grh < n) ((unsigned*)g_hh)[(size_t)grh * 64 + (cn >> 1)] = *(unsigned*)&phi;
    }
    psl += __shfl_xor_sync(0xffffffffu, psl, 1); psl += __shfl_xor_sync(0xffffffffu, psl, 2);
    pdl += __shfl_xor_sync(0xffffffffu, pdl, 1); pdl += __shfl_xor_sync(0xffffffffu, pdl, 2);
    psh += __shfl_xor_sync(0xffffffffu, psh, 1); psh += __shfl_xor_sync(0xffffffffu, psh, 2);
    pdh += __shfl_xor_sync(0xffffffffu, pdh, 1); pdh += __shfl_xor_sync(0xffffffffu, pdh, 2);
    int half = warp & 1;
    if (q == 0) {
        sdot_s[rl * 2 + half] = psl; sdot_d[rl * 2 + half] = pdl;
        sdot_s[rh * 2 + half] = psh; sdot_d[rh * 2 + half] = pdh;
    }
    __syncthreads();
    if (tid < 64) {
        int gr = row0 + tid;
        if (gr < n) {
            g_as[gr] = sdot_s[tid * 2] + sdot_s[tid * 2 + 1];
            g_ad[gr] = sdot_d[tid * 2] + sdot_d[tid * 2 + 1];
        }
    }
}

// ---------------- aggregation: warp per dst node ----------------
// Fast path (deg<=32): one edge per lane; softmax weights computed once in
// registers, then (src, w) broadcast via shfl during the h-row gather loop.
__global__ void __launch_bounds__(256)
agg_kernel(const float* __restrict__ bias, float* __restrict__ outext,
           int use_ext, int do_bn, int n) {
    __shared__ float sb_sum[D];
    __shared__ float sb_sq[D];
    if (do_bn) {
        if (threadIdx.x < D) { sb_sum[threadIdx.x] = 0.f; sb_sq[threadIdx.x] = 0.f; }
        __syncthreads();
    }
    int warp = threadIdx.x >> 5, lane = threadIdx.x & 31;
    int node = blockIdx.x * 8 + warp;
    float4 res = make_float4(0.f, 0.f, 0.f, 0.f);
    float* out = use_ext ? outext : g_x;
    const uint2* hb = g_hh;

    if (node < n) {
        int beg = g_rowptr[node], end = g_rowptr[node + 1];
        int deg = end - beg;
        float md = g_ad[node];
        float4 a0 = make_float4(0.f, 0.f, 0.f, 0.f);
        float4 a1 = make_float4(0.f, 0.f, 0.f, 0.f);
        float ssum;

        if (deg <= 32) {
            int src = 0;
            float e = -3.0e38f;
            if (lane < deg) {
                src = g_csr_src[beg + lane];
                e = g_as[src] + md;
                e = e > 0.f ? e : 0.2f * e;
            }
            float m = e;
            #pragma unroll
            for (int o = 16; o > 0; o >>= 1) m = fmaxf(m, __shfl_xor_sync(0xffffffffu, m, o));
            float w = (lane < deg) ? __expf(e - m) : 0.f;
            ssum = w;
            #pragma unroll
            for (int o = 16; o > 0; o >>= 1) ssum += __shfl_xor_sync(0xffffffffu, ssum, o);

            int kmax = deg;   // warp-uniform trip count
            int k = 0;
            for (; k + 4 <= kmax; k += 4) {
                int s0 = __shfl_sync(0xffffffffu, src, k);
                int s1 = __shfl_sync(0xffffffffu, src, k + 1);
                int s2 = __shfl_sync(0xffffffffu, src, k + 2);
                int s3 = __shfl_sync(0xffffffffu, src, k + 3);
                float w0 = __shfl_sync(0xffffffffu, w, k);
                float w1 = __shfl_sync(0xffffffffu, w, k + 1);
                float w2 = __shfl_sync(0xffffffffu, w, k + 2);
                float w3 = __shfl_sync(0xffffffffu, w, k + 3);
                uint2 p0 = hb[(size_t)s0 * 32 + lane];
                uint2 p1 = hb[(size_t)s1 * 32 + lane];
                uint2 p2 = hb[(size_t)s2 * 32 + lane];
                uint2 p3 = hb[(size_t)s3 * 32 + lane];
                float2 f;
                f = __half22float2(*(__half2*)&p0.x); a0.x += f.x * w0; a0.y += f.y * w0;
                f = __half22float2(*(__half2*)&p0.y); a0.z += f.x * w0; a0.w += f.y * w0;
                f = __half22float2(*(__half2*)&p1.x); a1.x += f.x * w1; a1.y += f.y * w1;
                f = __half22float2(*(__half2*)&p1.y); a1.z += f.x * w1; a1.w += f.y * w1;
                f = __half22float2(*(__half2*)&p2.x); a0.x += f.x * w2; a0.y += f.y * w2;
                f = __half22float2(*(__half2*)&p2.y); a0.z += f.x * w2; a0.w += f.y * w2;
                f = __half22float2(*(__half2*)&p3.x); a1.x += f.x * w3; a1.y += f.y * w3;
                f = __half22float2(*(__half2*)&p3.y); a1.z += f.x * w3; a1.w += f.y * w3;
            }
            for (; k < kmax; k++) {
                int s0 = __shfl_sync(0xffffffffu, src, k);
                float w0 = __shfl_sync(0xffffffffu, w, k);
                uint2 p0 = hb[(size_t)s0 * 32 + lane];
                float2 f;
                f = __half22float2(*(__half2*)&p0.x); a0.x += f.x * w0; a0.y += f.y * w0;
                f = __half22float2(*(__half2*)&p0.y); a0.z += f.x * w0; a0.w += f.y * w0;
            }
        } else {
            float m = -3.0e38f;
            for (int j = beg + lane; j < end; j += 32) {
                float e = g_as[g_csr_src[j]] + md;
                e = e > 0.f ? e : 0.2f * e;
                m = fmaxf(m, e);
            }
            #pragma unroll
            for (int o = 16; o > 0; o >>= 1) m = fmaxf(m, __shfl_xor_sync(0xffffffffu, m, o));
            ssum = 0.f;
            int j = beg;
            for (; j + 2 <= end; j += 2) {
                int s0 = g_csr_src[j], s1 = g_csr_src[j + 1];
                uint2 p0 = hb[(size_t)s0 * 32 + lane];
                uint2 p1 = hb[(size_t)s1 * 32 + lane];
                float e0 = g_as[s0] + md; e0 = e0 > 0.f ? e0 : 0.2f * e0;
                float e1 = g_as[s1] + md; e1 = e1 > 0.f ? e1 : 0.2f * e1;
                float w0 = __expf(e0 - m), w1 = __expf(e1 - m);
                ssum += w0 + w1;
                float2 f;
                f = __half22float2(*(__half2*)&p0.x); a0.x += f.x * w0; a0.y += f.y * w0;
                f = __half22float2(*(__half2*)&p0.y); a0.z += f.x * w0; a0.w += f.y * w0;
                f = __half22float2(*(__half2*)&p1.x); a1.x += f.x * w1; a1.y += f.y * w1;
                f = __half22float2(*(__half2*)&p1.y); a1.z += f.x * w1; a1.w += f.y * w1;
            }
            if (j < end) {
                int s0 = g_csr_src[j];
                uint2 p0 = hb[(size_t)s0 * 32 + lane];
                float e0 = g_as[s0] + md; e0 = e0 > 0.f ? e0 : 0.2f * e0;
                float w0 = __expf(e0 - m);
                ssum += w0;
                float2 f;
                f = __half22float2(*(__half2*)&p0.x); a0.x += f.x * w0; a0.y += f.y * w0;
                f = __half22float2(*(__half2*)&p0.y); a0.z += f.x * w0; a0.w += f.y * w0;
            }
        }

        float inv = 1.f / (ssum + 1e-16f);
        float4 b4 = ((const float4*)bias)[lane];
        res.x = (a0.x + a1.x) * inv + b4.x;
        res.y = (a0.y + a1.y) * inv + b4.y;
        res.z = (a0.z + a1.z) * inv + b4.z;
        res.w = (a0.w + a1.w) * inv + b4.w;
        *((float4*)(out + (size_t)node * D + lane * 4)) = res;
    }

    if (do_bn) {
        if (node < n) {
            int ch = lane * 4;
            atomicAdd(&sb_sum[ch + 0], res.x); atomicAdd(&sb_sq[ch + 0], res.x * res.x);
            atomicAdd(&sb_sum[ch + 1], res.y); atomicAdd(&sb_sq[ch + 1], res.y * res.y);
            atomicAdd(&sb_sum[ch + 2], res.z); atomicAdd(&sb_sq[ch + 2], res.z * res.z);
            atomicAdd(&sb_sum[ch + 3], res.w); atomicAdd(&sb_sq[ch + 3], res.w * res.w);
        }
        __syncthreads();
        if (threadIdx.x < D) {
            atomicAdd(&g_bnsum[threadIdx.x], sb_sum[threadIdx.x]);
            atomicAdd(&g_bnsq[threadIdx.x], sb_sq[threadIdx.x]);
        }
    }
}

__global__ void bn_finalize_kernel(const float* __restrict__ gamma,
                                   const float* __restrict__ beta, float inv_n) {
    int c = threadIdx.x;
    float mean = g_bnsum[c] * inv_n;
    float var = g_bnsq[c] * inv_n - mean * mean;
    float sc = gamma[c] * rsqrtf(var + 1e-5f);
    g_scale[c] = sc;
    g_shift[c] = beta[c] - mean * sc;
    g_bnsum[c] = 0.f;
    g_bnsq[c] = 0.f;
}

// ---------------- launch ----------------
extern "C" void kernel_launch(void* const* d_in, const int* in_sizes, int n_in,
                              void* d_out, int out_size) {
    const float* x    = (const float*)d_in[0];
    const void*  ei   = d_in[1];
    const float* Ws   = (const float*)d_in[2];
    const float* a_s  = (const float*)d_in[3];
    const float* a_d  = (const float*)d_in[4];
    const float* bias = (const float*)d_in[5];
    const float* gam  = (const float*)d_in[6];
    const float* bet  = (const float*)d_in[7];
    float* out = (float*)d_out;

    int n = in_sizes[0] / D;
    int E = in_sizes[1] / 2;

    int nblk = (n + 255) / 256;
    int eblk = (E + 255) / 256;
    int gblk = (n + 63) / 64;
    int ablk = (n + 7) / 8;
    int sblk = (n + SCAN_CHUNK - 1) / SCAN_CHUNK;
    float inv_n = 1.0f / (float)n;

    // CSR build + W prep
    zero_kernel<<<nblk, 256>>>((const unsigned*)ei, n);
    prep_w_kernel<<<(3 * D * D + 255) / 256, 256>>>(Ws);
    count_kernel<<<eblk, 256>>>(ei, E);
    scan_reduce_kernel<<<sblk, 1024>>>(n);
    scan_top_kernel<<<1, 1024>>>(sblk, n);
    scan_apply_kernel<<<sblk, 1024>>>(n);
    scatter_kernel<<<eblk, 256>>>(ei, E);

    // layer 0
    gemm_kernel<<<gblk, 256>>>(x, 1, 0, a_s, a_d, 0, n);
    agg_kernel<<<ablk, 256>>>(bias, nullptr, 0, 1, n);
    bn_finalize_kernel<<<1, D>>>(gam, bet, inv_n);
    // layer 1
    gemm_kernel<<<gblk, 256>>>(nullptr, 0, 1, a_s + D, a_d + D, 1, n);
    agg_kernel<<<ablk, 256>>>(bias + D, nullptr, 0, 1, n);
    bn_finalize_kernel<<<1, D>>>(gam + D, bet + D, inv_n);
    // layer 2
    gemm_kernel<<<gblk, 256>>>(nullptr, 0, 2, a_s + 2 * D, a_d + 2 * D, 1, n);
    agg_kernel<<<ablk, 256>>>(bias + 2 * D, out, 1, 0, n);
}